// round 1
// baseline (speedup 1.0000x reference)
#include <cuda_runtime.h>
#include <cstdint>
#include <math.h>

// Problem constants
#define BB 64
#define NPTS 2048
#define KTOT 98304          // NPTS * 48
#define NOUT 1000
#define IMG_H 1024
#define IMG_W 1024

// SGEMM tiling
#define KSPLIT 192
#define KC 512              // K per block (KSPLIT * KC == KTOT)
#define KB 16               // K per smem stage
#define NT 256              // N tile per block
#define NSTAGES (KC / KB)   // 32

// ---------------- scratch (static device globals; no runtime alloc) ----------
__device__ float g_xy[BB * NPTS * 2];                      // 1 MB, float2 per point
__device__ float g_AT[(size_t)KTOT * BB];                  // 25.2 MB, AT[k][m]
__device__ float g_partial[(size_t)KSPLIT * BB * NOUT];    // 49.2 MB

// ---------------- helpers ----------------------------------------------------
__device__ __forceinline__ void cp16(uint32_t dst, const void* src, int src_size) {
    asm volatile("cp.async.cg.shared.global [%0], [%1], 16, %2;"
                 :: "r"(dst), "l"(src), "r"(src_size));
}
__device__ __forceinline__ void fma2(unsigned long long& d,
                                     unsigned long long a,
                                     unsigned long long b) {
    asm volatile("fma.rn.f32x2 %0, %1, %2, %0;" : "+l"(d) : "l"(a), "l"(b));
}
__device__ __forceinline__ unsigned long long pack2(float x) {
    unsigned long long r;
    asm("mov.b64 %0, {%1, %1};" : "=l"(r) : "f"(x));
    return r;
}

// ---------------- kernel 1: resize + coords GEMM + sigmoid --------------------
__global__ void coords_kernel(const float* __restrict__ tv_img,
                              const float* __restrict__ w1,
                              const float* __restrict__ b1) {
    __shared__ float tv[48];
    int b = blockIdx.x;
    int tid = threadIdx.x;
    if (tid < 48) {
        int c = tid >> 4, rem = tid & 15, i = rem >> 2, j = rem & 3;
        int r0 = 7 + 16 * i, c0 = 7 + 16 * j;
        const float* base = tv_img + ((size_t)(b * 3 + c) * 64) * 64;
        // resize axis2 (rows) first, then axis3 (cols) — matches reference rounding
        float t0 = 0.5f * base[r0 * 64 + c0]     + 0.5f * base[(r0 + 1) * 64 + c0];
        float t1 = 0.5f * base[r0 * 64 + c0 + 1] + 0.5f * base[(r0 + 1) * 64 + c0 + 1];
        tv[tid] = 0.5f * t0 + 0.5f * t1;
    }
    __syncthreads();

    const float2* w1v = (const float2*)w1;   // (48, 2048) of float2 (n-pairs)
    const float2* b1v = (const float2*)b1;
    float2* xy = (float2*)g_xy;

    for (int n = tid; n < NPTS; n += blockDim.x) {
        float2 l = b1v[n];
        #pragma unroll
        for (int f = 0; f < 48; f++) {
            float2 w = w1v[(size_t)f * NPTS + n];
            l.x += tv[f] * w.x;
            l.y += tv[f] * w.y;
        }
        float sx = 1.0f / (1.0f + expf(-l.x));   // accurate expf: keep coord error ~1e-7
        float sy = 1.0f / (1.0f + expf(-l.y));
        float2 p;
        p.x = sx * 1019.0f + 2.0f;               // (H-1-PATCH) + PATCH/2
        p.y = sy * 1019.0f + 2.0f;
        xy[(size_t)b * NPTS + n] = p;
    }
}

// ---------------- kernel 2: bilinear patch gather -> AT[k][m] -----------------
// block (64, 4): threadIdx.x = batch b (coalesced stores), threadIdx.y = n-sub
__global__ void gather_kernel(const float* __restrict__ search) {
    int b = threadIdx.x;
    int n = blockIdx.x * 4 + threadIdx.y;

    const float2* xy = (const float2*)g_xy;
    float2 p = xy[(size_t)b * NPTS + n];
    float x0 = floorf(p.x), y0 = floorf(p.y);
    float fx = p.x - x0, fy = p.y - y0;
    int ix = (int)x0 - 2, iy = (int)y0 - 2;   // always in-bounds (coords in (0,1))
    float wx0 = 1.0f - fx, wy0 = 1.0f - fy;

    const float* img = search + (size_t)b * (IMG_H * IMG_W * 3);

    float rowT[15], rowB[15];
    {
        const float* rp = img + ((size_t)ix * IMG_W + iy) * 3;
        #pragma unroll
        for (int t = 0; t < 15; t++) rowT[t] = __ldg(rp + t);
    }
    float* outbase = g_AT + (size_t)n * 48 * BB + b;

    #pragma unroll
    for (int i = 0; i < 4; i++) {
        const float* rp = img + ((size_t)(ix + i + 1) * IMG_W + iy) * 3;
        #pragma unroll
        for (int t = 0; t < 15; t++) rowB[t] = __ldg(rp + t);
        #pragma unroll
        for (int j = 0; j < 4; j++) {
            #pragma unroll
            for (int ch = 0; ch < 3; ch++) {
                float top = wy0 * rowT[j * 3 + ch] + fy * rowT[j * 3 + 3 + ch];
                float bot = wy0 * rowB[j * 3 + ch] + fy * rowB[j * 3 + 3 + ch];
                float v = wx0 * top + fx * bot;
                outbase[(size_t)(i * 12 + j * 3 + ch) * BB] = v;
            }
        }
        #pragma unroll
        for (int t = 0; t < 15; t++) rowT[t] = rowB[t];
    }
}

// ---------------- kernel 3: split-K SGEMM with fma.f32x2 ----------------------
// C_partial(64 x NT) += AT_chunk(KC x 64)^T @ W2_chunk(KC x NT)
// 128 threads: thread tile 8m x 16n, acc as f32x2 pairs over n.
__global__ void __launch_bounds__(128) sgemm_kernel(const float* __restrict__ w2) {
    __shared__ float sA[2][KB][64];    // 8 KB
    __shared__ float sB[2][KB][NT];    // 32 KB

    int tid = threadIdx.x;
    int n0 = blockIdx.x * NT;
    int ks = blockIdx.y;
    int k0 = ks * KC;
    int tx = tid & 15;     // n group (16 cols each)
    int ty = tid >> 4;     // m group (8 rows each)
    int nf4 = n0 >> 2;

    uint32_t sAaddr = (uint32_t)__cvta_generic_to_shared(&sA[0][0][0]);
    uint32_t sBaddr = (uint32_t)__cvta_generic_to_shared(&sB[0][0][0]);

    unsigned long long acc[8][8];
    #pragma unroll
    for (int m = 0; m < 8; m++)
        #pragma unroll
        for (int q = 0; q < 8; q++) acc[m][q] = 0ull;

    auto prefetch = [&](int s, int kidx) {
        int kbase = k0 + kidx * KB;
        const float4* srcA = (const float4*)(g_AT + (size_t)kbase * 64);
        uint32_t dA = sAaddr + (uint32_t)s * (KB * 64 * 4);
        #pragma unroll
        for (int i = 0; i < 2; i++) {
            int g = tid + 128 * i;
            cp16(dA + g * 16, srcA + g, 16);
        }
        uint32_t dB = sBaddr + (uint32_t)s * (KB * NT * 4);
        #pragma unroll
        for (int i = 0; i < 8; i++) {
            int g = tid + 128 * i;
            int kk = g >> 6;
            int col = g & 63;
            int v = (nf4 + col) < (NOUT / 4) ? 16 : 0;  // NOUT=1000 -> 250 float4 per row
            int colc = v ? col : 0;
            const float4* srcB =
                (const float4*)(w2 + (size_t)(kbase + kk) * NOUT + n0) + colc;
            cp16(dB + g * 16, srcB, v);
        }
        asm volatile("cp.async.commit_group;");
    };

    prefetch(0, 0);
    for (int s = 0; s < NSTAGES; s++) {
        if (s + 1 < NSTAGES) {
            prefetch((s + 1) & 1, s + 1);
            asm volatile("cp.async.wait_group 1;");
        } else {
            asm volatile("cp.async.wait_group 0;");
        }
        __syncthreads();
        int buf = s & 1;
        #pragma unroll
        for (int kk = 0; kk < KB; kk++) {
            float4 a0 = *(const float4*)&sA[buf][kk][ty * 8];
            float4 a1 = *(const float4*)&sA[buf][kk][ty * 8 + 4];
            unsigned long long ap[8];
            ap[0] = pack2(a0.x); ap[1] = pack2(a0.y);
            ap[2] = pack2(a0.z); ap[3] = pack2(a0.w);
            ap[4] = pack2(a1.x); ap[5] = pack2(a1.y);
            ap[6] = pack2(a1.z); ap[7] = pack2(a1.w);
            unsigned long long bp[8];
            const ulonglong2* bsrc = (const ulonglong2*)&sB[buf][kk][tx * 16];
            #pragma unroll
            for (int q = 0; q < 4; q++) {
                ulonglong2 t = bsrc[q];
                bp[2 * q] = t.x; bp[2 * q + 1] = t.y;
            }
            #pragma unroll
            for (int m = 0; m < 8; m++)
                #pragma unroll
                for (int q = 0; q < 8; q++)
                    fma2(acc[m][q], ap[m], bp[q]);
        }
        __syncthreads();
    }

    // epilogue: write partials
    float* dst = g_partial + (size_t)ks * BB * NOUT;
    #pragma unroll
    for (int m = 0; m < 8; m++) {
        int mm = ty * 8 + m;
        float* row = dst + (size_t)mm * NOUT + n0;
        #pragma unroll
        for (int g4 = 0; g4 < 4; g4++) {
            int col = tx * 16 + g4 * 4;
            if (n0 + col < NOUT) {
                float4 v;
                asm("mov.b64 {%0,%1}, %4;\n\t"
                    "mov.b64 {%2,%3}, %5;"
                    : "=f"(v.x), "=f"(v.y), "=f"(v.z), "=f"(v.w)
                    : "l"(acc[m][2 * g4]), "l"(acc[m][2 * g4 + 1]));
                *(float4*)(row + col) = v;
            }
        }
    }
}

// ---------------- kernel 4: reduce partials + bias ---------------------------
__global__ void reduce_kernel(const float* __restrict__ b2, float* __restrict__ out) {
    int idx = blockIdx.x * 256 + threadIdx.x;
    if (idx >= BB * NOUT) return;
    int o = idx % NOUT;
    float s = b2[o];
    const float* p = g_partial + idx;
    #pragma unroll 8
    for (int ks = 0; ks < KSPLIT; ks++) s += p[(size_t)ks * (BB * NOUT)];
    out[idx] = s;
}

// ---------------- launch ------------------------------------------------------
extern "C" void kernel_launch(void* const* d_in, const int* in_sizes, int n_in,
                              void* d_out, int out_size) {
    const float* topview = (const float*)d_in[0];
    const float* search  = (const float*)d_in[1];
    const float* w1      = (const float*)d_in[2];
    const float* b1      = (const float*)d_in[3];
    const float* w2      = (const float*)d_in[4];
    const float* b2      = (const float*)d_in[5];
    float* out = (float*)d_out;

    coords_kernel<<<BB, 512>>>(topview, w1, b1);
    gather_kernel<<<NPTS / 4, dim3(64, 4)>>>(search);
    sgemm_kernel<<<dim3(NT == 256 ? 4 : (NOUT + NT - 1) / NT, KSPLIT), 128>>>(w2);
    reduce_kernel<<<(BB * NOUT + 255) / 256, 256>>>(b2, out);
}

// round 2
// speedup vs baseline: 1.4461x; 1.4461x over previous
#include <cuda_runtime.h>
#include <cstdint>
#include <math.h>

// Problem constants
#define BB 64
#define NPTS 2048
#define KTOT 98304          // NPTS * 48
#define NOUT 1000
#define IMG_H 1024
#define IMG_W 1024

// SGEMM tiling
#define KSPLIT 96
#define KC 1024             // K per block (KSPLIT * KC == KTOT)
#define KB 16               // K per smem stage
#define NT 256              // N tile per block
#define NSTAGES (KC / KB)   // 64

// ---------------- scratch (static device globals; no runtime alloc) ----------
__device__ float g_xy[BB * NPTS * 2];                      // 1 MB, float2 per point
__device__ float g_AT[(size_t)KTOT * BB];                  // 25.2 MB, AT[k][m]
__device__ float g_partial[(size_t)KSPLIT * BB * NOUT];    // 24.6 MB

// ---------------- helpers ----------------------------------------------------
__device__ __forceinline__ void cp16(uint32_t dst, const void* src, int src_size) {
    asm volatile("cp.async.cg.shared.global [%0], [%1], 16, %2;"
                 :: "r"(dst), "l"(src), "r"(src_size));
}
__device__ __forceinline__ void fma2(unsigned long long& d,
                                     unsigned long long a,
                                     unsigned long long b) {
    asm volatile("fma.rn.f32x2 %0, %1, %2, %0;" : "+l"(d) : "l"(a), "l"(b));
}
__device__ __forceinline__ unsigned long long pack2(float x) {
    unsigned long long r;
    asm("mov.b64 %0, {%1, %1};" : "=l"(r) : "f"(x));
    return r;
}

// ---------------- kernel 1: resize + coords GEMM + sigmoid --------------------
__global__ void coords_kernel(const float* __restrict__ tv_img,
                              const float* __restrict__ w1,
                              const float* __restrict__ b1) {
    __shared__ float tv[48];
    int b = blockIdx.x;
    int tid = threadIdx.x;
    if (tid < 48) {
        int c = tid >> 4, rem = tid & 15, i = rem >> 2, j = rem & 3;
        int r0 = 7 + 16 * i, c0 = 7 + 16 * j;
        const float* base = tv_img + ((size_t)(b * 3 + c) * 64) * 64;
        float t0 = 0.5f * base[r0 * 64 + c0]     + 0.5f * base[(r0 + 1) * 64 + c0];
        float t1 = 0.5f * base[r0 * 64 + c0 + 1] + 0.5f * base[(r0 + 1) * 64 + c0 + 1];
        tv[tid] = 0.5f * t0 + 0.5f * t1;
    }
    __syncthreads();

    const float2* w1v = (const float2*)w1;   // (48, 2048) of float2 (n-pairs)
    const float2* b1v = (const float2*)b1;
    float2* xy = (float2*)g_xy;

    for (int n = tid; n < NPTS; n += blockDim.x) {
        float2 l = b1v[n];
        #pragma unroll
        for (int f = 0; f < 48; f++) {
            float2 w = w1v[(size_t)f * NPTS + n];
            l.x += tv[f] * w.x;
            l.y += tv[f] * w.y;
        }
        float sx = 1.0f / (1.0f + expf(-l.x));
        float sy = 1.0f / (1.0f + expf(-l.y));
        float2 p;
        p.x = sx * 1019.0f + 2.0f;               // (H-1-PATCH) + PATCH/2
        p.y = sy * 1019.0f + 2.0f;
        xy[(size_t)b * NPTS + n] = p;
    }
}

// ---------------- kernel 2: bilinear patch gather -> AT[k][m] -----------------
__global__ void gather_kernel(const float* __restrict__ search) {
    int b = threadIdx.x;
    int n = blockIdx.x * 4 + threadIdx.y;

    const float2* xy = (const float2*)g_xy;
    float2 p = xy[(size_t)b * NPTS + n];
    float x0 = floorf(p.x), y0 = floorf(p.y);
    float fx = p.x - x0, fy = p.y - y0;
    int ix = (int)x0 - 2, iy = (int)y0 - 2;
    float wx0 = 1.0f - fx, wy0 = 1.0f - fy;

    const float* img = search + (size_t)b * (IMG_H * IMG_W * 3);

    float rowT[15], rowB[15];
    {
        const float* rp = img + ((size_t)ix * IMG_W + iy) * 3;
        #pragma unroll
        for (int t = 0; t < 15; t++) rowT[t] = __ldg(rp + t);
    }
    float* outbase = g_AT + (size_t)n * 48 * BB + b;

    #pragma unroll
    for (int i = 0; i < 4; i++) {
        const float* rp = img + ((size_t)(ix + i + 1) * IMG_W + iy) * 3;
        #pragma unroll
        for (int t = 0; t < 15; t++) rowB[t] = __ldg(rp + t);
        #pragma unroll
        for (int j = 0; j < 4; j++) {
            #pragma unroll
            for (int ch = 0; ch < 3; ch++) {
                float top = wy0 * rowT[j * 3 + ch] + fy * rowT[j * 3 + 3 + ch];
                float bot = wy0 * rowB[j * 3 + ch] + fy * rowB[j * 3 + 3 + ch];
                float v = wx0 * top + fx * bot;
                outbase[(size_t)(i * 12 + j * 3 + ch) * BB] = v;
            }
        }
        #pragma unroll
        for (int t = 0; t < 15; t++) rowT[t] = rowB[t];
    }
}

// ---------------- kernel 3: split-K SGEMM with fma.f32x2 ----------------------
// Thread tile: 8 m-rows x 16 n-cols, but n-cols are {tx*4 + 64*q, q=0..3}
// so the per-q B fragment loads are 16 contiguous 16B chunks -> conflict-free.
__global__ void __launch_bounds__(128) sgemm_kernel(const float* __restrict__ w2) {
    __shared__ float sA[2][KB][64];    // 8 KB
    __shared__ float sB[2][KB][NT];    // 32 KB

    int tid = threadIdx.x;
    int n0 = blockIdx.x * NT;
    int ks = blockIdx.y;
    int k0 = ks * KC;
    int tx = tid & 15;     // n sub-column (4 floats each, at 64-col stride)
    int ty = tid >> 4;     // m group (8 rows each)
    int nf4 = n0 >> 2;

    uint32_t sAaddr = (uint32_t)__cvta_generic_to_shared(&sA[0][0][0]);
    uint32_t sBaddr = (uint32_t)__cvta_generic_to_shared(&sB[0][0][0]);

    unsigned long long acc[8][8];
    #pragma unroll
    for (int m = 0; m < 8; m++)
        #pragma unroll
        for (int q = 0; q < 8; q++) acc[m][q] = 0ull;

    auto prefetch = [&](int s, int kidx) {
        int kbase = k0 + kidx * KB;
        const float4* srcA = (const float4*)(g_AT + (size_t)kbase * 64);
        uint32_t dA = sAaddr + (uint32_t)s * (KB * 64 * 4);
        #pragma unroll
        for (int i = 0; i < 2; i++) {
            int g = tid + 128 * i;
            cp16(dA + g * 16, srcA + g, 16);
        }
        uint32_t dB = sBaddr + (uint32_t)s * (KB * NT * 4);
        #pragma unroll
        for (int i = 0; i < 8; i++) {
            int g = tid + 128 * i;
            int kk = g >> 6;
            int col = g & 63;
            int v = (nf4 + col) < (NOUT / 4) ? 16 : 0;  // zero-fill cols >= 1000
            int colc = v ? col : 0;
            const float4* srcB =
                (const float4*)(w2 + (size_t)(kbase + kk) * NOUT + n0) + colc;
            cp16(dB + g * 16, srcB, v);
        }
        asm volatile("cp.async.commit_group;");
    };

    prefetch(0, 0);
    for (int s = 0; s < NSTAGES; s++) {
        if (s + 1 < NSTAGES) {
            prefetch((s + 1) & 1, s + 1);
            asm volatile("cp.async.wait_group 1;");
        } else {
            asm volatile("cp.async.wait_group 0;");
        }
        __syncthreads();
        int buf = s & 1;
        #pragma unroll
        for (int kk = 0; kk < KB; kk++) {
            float4 a0 = *(const float4*)&sA[buf][kk][ty * 8];
            float4 a1 = *(const float4*)&sA[buf][kk][ty * 8 + 4];
            unsigned long long ap[8];
            ap[0] = pack2(a0.x); ap[1] = pack2(a0.y);
            ap[2] = pack2(a0.z); ap[3] = pack2(a0.w);
            ap[4] = pack2(a1.x); ap[5] = pack2(a1.y);
            ap[6] = pack2(a1.z); ap[7] = pack2(a1.w);
            unsigned long long bp[8];
            #pragma unroll
            for (int q = 0; q < 4; q++) {
                // conflict-free: 16 threads read 16 contiguous 16B chunks
                ulonglong2 t = *(const ulonglong2*)&sB[buf][kk][tx * 4 + q * 64];
                bp[2 * q] = t.x; bp[2 * q + 1] = t.y;
            }
            #pragma unroll
            for (int m = 0; m < 8; m++)
                #pragma unroll
                for (int q = 0; q < 8; q++)
                    fma2(acc[m][q], ap[m], bp[q]);
        }
        __syncthreads();
    }

    // epilogue: write partials. acc[m][2q..2q+1] -> cols n0 + tx*4 + q*64
    float* dst = g_partial + (size_t)ks * BB * NOUT;
    #pragma unroll
    for (int m = 0; m < 8; m++) {
        int mm = ty * 8 + m;
        float* row = dst + (size_t)mm * NOUT + n0;
        #pragma unroll
        for (int q = 0; q < 4; q++) {
            int col = tx * 4 + q * 64;
            if (n0 + col < NOUT) {
                float4 v;
                asm("mov.b64 {%0,%1}, %4;\n\t"
                    "mov.b64 {%2,%3}, %5;"
                    : "=f"(v.x), "=f"(v.y), "=f"(v.z), "=f"(v.w)
                    : "l"(acc[m][2 * q]), "l"(acc[m][2 * q + 1]));
                *(float4*)(row + col) = v;
            }
        }
    }
}

// ---------------- kernel 4: reduce partials + bias (float4) -------------------
__global__ void reduce_kernel(const float* __restrict__ b2, float* __restrict__ out) {
    int idx4 = blockIdx.x * 256 + threadIdx.x;
    if (idx4 >= (BB * NOUT) / 4) return;
    int o = (idx4 * 4) % NOUT;     // 4 | NOUT, never crosses a row
    float4 s = *(const float4*)(b2 + o);
    const float4* p = (const float4*)g_partial + idx4;
    #pragma unroll 8
    for (int ks = 0; ks < KSPLIT; ks++) {
        float4 v = p[(size_t)ks * (BB * NOUT / 4)];
        s.x += v.x; s.y += v.y; s.z += v.z; s.w += v.w;
    }
    ((float4*)out)[idx4] = s;
}

// ---------------- launch ------------------------------------------------------
extern "C" void kernel_launch(void* const* d_in, const int* in_sizes, int n_in,
                              void* d_out, int out_size) {
    const float* topview = (const float*)d_in[0];
    const float* search  = (const float*)d_in[1];
    const float* w1      = (const float*)d_in[2];
    const float* b1      = (const float*)d_in[3];
    const float* w2      = (const float*)d_in[4];
    const float* b2      = (const float*)d_in[5];
    float* out = (float*)d_out;

    coords_kernel<<<BB, 512>>>(topview, w1, b1);
    gather_kernel<<<NPTS / 4, dim3(64, 4)>>>(search);
    sgemm_kernel<<<dim3((NOUT + NT - 1) / NT, KSPLIT), 128>>>(w2);
    reduce_kernel<<<(BB * NOUT / 4 + 255) / 256, 256>>>(b2, out);
}

// round 5
// speedup vs baseline: 1.4798x; 1.0233x over previous
#include <cuda_runtime.h>
#include <cstdint>
#include <math.h>

// Problem constants
#define BB 64
#define NPTS 2048
#define KTOT 98304          // NPTS * 48
#define NOUT 1000
#define IMG_H 1024
#define IMG_W 1024

// SGEMM tiling: grid = 4 n-tiles x 74 k-splits = 296 CTAs = 2/SM, one wave
#define KSPLIT 74
#define KB 16               // K rows per smem stage
#define NCHTOT (KTOT / KB)  // 6144 chunks total
#define CHBASE 83           // chunks per CTA (first 2 CTAs get 84)
#define NT 256              // N tile per block

// ---------------- scratch (static device globals; no runtime alloc) ----------
__device__ float g_xy[BB * NPTS * 2];                      // float2 per point
__device__ float g_AT[(size_t)KTOT * BB];                  // 25.2 MB, AT[k][m]
__device__ float g_partial[(size_t)KSPLIT * BB * 1024];    // 19.4 MB (N padded 1024)

// ---------------- helpers ----------------------------------------------------
__device__ __forceinline__ void cp16(uint32_t dst, const void* src, int src_size) {
    asm volatile("cp.async.cg.shared.global [%0], [%1], 16, %2;"
                 :: "r"(dst), "l"(src), "r"(src_size));
}
__device__ __forceinline__ void fma2(unsigned long long& d,
                                     unsigned long long a,
                                     unsigned long long b) {
    asm volatile("fma.rn.f32x2 %0, %1, %2, %0;" : "+l"(d) : "l"(a), "l"(b));
}
__device__ __forceinline__ unsigned long long pack2(float x) {
    unsigned long long r;
    asm("mov.b64 %0, {%1, %1};" : "=l"(r) : "f"(x));
    return r;
}

// ---------------- kernel 1: resize + coords GEMM + sigmoid --------------------
__global__ void coords_kernel(const float* __restrict__ tv_img,
                              const float* __restrict__ w1,
                              const float* __restrict__ b1) {
    __shared__ float tv[48];
    int b = blockIdx.x;
    int tid = threadIdx.x;
    if (tid < 48) {
        int c = tid >> 4, rem = tid & 15, i = rem >> 2, j = rem & 3;
        int r0 = 7 + 16 * i, c0 = 7 + 16 * j;
        const float* base = tv_img + ((size_t)(b * 3 + c) * 64) * 64;
        float t0 = 0.5f * base[r0 * 64 + c0]     + 0.5f * base[(r0 + 1) * 64 + c0];
        float t1 = 0.5f * base[r0 * 64 + c0 + 1] + 0.5f * base[(r0 + 1) * 64 + c0 + 1];
        tv[tid] = 0.5f * t0 + 0.5f * t1;
    }
    __syncthreads();

    const float2* w1v = (const float2*)w1;
    const float2* b1v = (const float2*)b1;
    float2* xy = (float2*)g_xy;

    for (int n = tid; n < NPTS; n += blockDim.x) {
        float2 l = b1v[n];
        #pragma unroll
        for (int f = 0; f < 48; f++) {
            float2 w = w1v[(size_t)f * NPTS + n];
            l.x += tv[f] * w.x;
            l.y += tv[f] * w.y;
        }
        float sx = 1.0f / (1.0f + expf(-l.x));
        float sy = 1.0f / (1.0f + expf(-l.y));
        float2 p;
        p.x = sx * 1019.0f + 2.0f;               // (H-1-PATCH) + PATCH/2
        p.y = sy * 1019.0f + 2.0f;
        xy[(size_t)b * NPTS + n] = p;
    }
}

// ---------------- kernel 2: bilinear patch gather -> AT[k][m] -----------------
__global__ void gather_kernel(const float* __restrict__ search) {
    int b = threadIdx.x;
    int n = blockIdx.x * 4 + threadIdx.y;

    const float2* xy = (const float2*)g_xy;
    float2 p = xy[(size_t)b * NPTS + n];
    float x0 = floorf(p.x), y0 = floorf(p.y);
    float fx = p.x - x0, fy = p.y - y0;
    int ix = (int)x0 - 2, iy = (int)y0 - 2;
    float wx0 = 1.0f - fx, wy0 = 1.0f - fy;

    const float* img = search + (size_t)b * (IMG_H * IMG_W * 3);

    float rowT[15], rowB[15];
    {
        const float* rp = img + ((size_t)ix * IMG_W + iy) * 3;
        #pragma unroll
        for (int t = 0; t < 15; t++) rowT[t] = __ldg(rp + t);
    }
    float* outbase = g_AT + (size_t)n * 48 * BB + b;

    #pragma unroll
    for (int i = 0; i < 4; i++) {
        const float* rp = img + ((size_t)(ix + i + 1) * IMG_W + iy) * 3;
        #pragma unroll
        for (int t = 0; t < 15; t++) rowB[t] = __ldg(rp + t);
        #pragma unroll
        for (int j = 0; j < 4; j++) {
            #pragma unroll
            for (int ch = 0; ch < 3; ch++) {
                float top = wy0 * rowT[j * 3 + ch] + fy * rowT[j * 3 + 3 + ch];
                float bot = wy0 * rowB[j * 3 + ch] + fy * rowB[j * 3 + 3 + ch];
                float v = wx0 * top + fx * bot;
                outbase[(size_t)(i * 12 + j * 3 + ch) * BB] = v;
            }
        }
        #pragma unroll
        for (int t = 0; t < 15; t++) rowT[t] = rowB[t];
    }
}

// ---------------- kernel 3: split-K SGEMM, 256 thr, 2 CTAs/SM -----------------
// Thread tile 4m x 16n; n-cols {tx*4 + 64q}; conflict-free smem on both operands.
__global__ void __launch_bounds__(256, 2) sgemm_kernel(const float* __restrict__ w2) {
    __shared__ float sA[2][KB][64];    // 8 KB
    __shared__ float sB[2][KB][NT];    // 32 KB

    int tid = threadIdx.x;
    int nt = blockIdx.x;
    int ks = blockIdx.y;
    int n0 = nt * NT;
    int c0 = ks * CHBASE + min(ks, 2);         // chunk start
    int nch = CHBASE + (ks < 2 ? 1 : 0);       // chunks this CTA
    int tx = tid & 15;     // n sub-column (4 floats, stride-64 groups)
    int ty = tid >> 4;     // m group (4 rows each)

    uint32_t sAaddr = (uint32_t)__cvta_generic_to_shared(&sA[0][0][0]);
    uint32_t sBaddr = (uint32_t)__cvta_generic_to_shared(&sB[0][0][0]);

    unsigned long long acc[4][8];
    #pragma unroll
    for (int m = 0; m < 4; m++)
        #pragma unroll
        for (int q = 0; q < 8; q++) acc[m][q] = 0ull;

    auto prefetch = [&](int s, int cidx) {
        int kbase = (c0 + cidx) * KB;
        // A: 16 rows x 64 f32 = 256 float4, one per thread
        cp16(sAaddr + (uint32_t)s * (KB * 64 * 4) + tid * 16,
             g_AT + (size_t)kbase * 64 + tid * 4, 16);
        // B: 16 rows x 256 f32 = 1024 float4, 4 per thread
        uint32_t dB = sBaddr + (uint32_t)s * (KB * NT * 4);
        #pragma unroll
        for (int i = 0; i < 4; i++) {
            int g = tid + 256 * i;
            int kk = g >> 6;
            int c4 = g & 63;
            int col = n0 + c4 * 4;
            int v = (col + 3 < NOUT) ? 16 : 0;   // zero-fill cols >= 1000
            const float* src = w2 + (size_t)(kbase + kk) * NOUT + (v ? col : 0);
            cp16(dB + g * 16, src, v);
        }
        asm volatile("cp.async.commit_group;");
    };

    prefetch(0, 0);
    for (int s = 0; s < nch; s++) {
        if (s + 1 < nch) {
            prefetch((s + 1) & 1, s + 1);
            asm volatile("cp.async.wait_group 1;");
        } else {
            asm volatile("cp.async.wait_group 0;");
        }
        __syncthreads();
        int buf = s & 1;
        #pragma unroll
        for (int kk = 0; kk < KB; kk++) {
            float4 a4 = *(const float4*)&sA[buf][kk][ty * 4];
            unsigned long long ap[4];
            ap[0] = pack2(a4.x); ap[1] = pack2(a4.y);
            ap[2] = pack2(a4.z); ap[3] = pack2(a4.w);
            unsigned long long bp[8];
            #pragma unroll
            for (int q = 0; q < 4; q++) {
                ulonglong2 t = *(const ulonglong2*)&sB[buf][kk][tx * 4 + q * 64];
                bp[2 * q] = t.x; bp[2 * q + 1] = t.y;
            }
            #pragma unroll
            for (int m = 0; m < 4; m++)
                #pragma unroll
                for (int q = 0; q < 8; q++)
                    fma2(acc[m][q], ap[m], bp[q]);
        }
        __syncthreads();
    }

    // epilogue: write partials (N padded to 1024; cols >=1000 are junk, ignored)
    float* dst = g_partial + (size_t)ks * BB * 1024;
    #pragma unroll
    for (int m = 0; m < 4; m++) {
        int mm = ty * 4 + m;
        float* row = dst + (size_t)mm * 1024 + n0;
        #pragma unroll
        for (int q = 0; q < 4; q++) {
            int col = tx * 4 + q * 64;
            float4 v;
            asm("mov.b64 {%0,%1}, %4;\n\t"
                "mov.b64 {%2,%3}, %5;"
                : "=f"(v.x), "=f"(v.y), "=f"(v.z), "=f"(v.w)
                : "l"(acc[m][2 * q]), "l"(acc[m][2 * q + 1]));
            *(float4*)(row + col) = v;
        }
    }
}

// ---------------- kernel 4: reduce partials + bias (float4) -------------------
__global__ void reduce_kernel(const float* __restrict__ b2, float* __restrict__ out) {
    int idx4 = blockIdx.x * 128 + threadIdx.x;   // over 64 * 250 float4s
    if (idx4 >= BB * (NOUT / 4)) return;
    int m = idx4 / (NOUT / 4);
    int o4 = idx4 % (NOUT / 4);
    float4 s = *(const float4*)(b2 + o4 * 4);
    const float* p = g_partial + (size_t)m * 1024 + o4 * 4;
    #pragma unroll 8
    for (int ks = 0; ks < KSPLIT; ks++) {
        float4 v = *(const float4*)(p + (size_t)ks * (BB * 1024));
        s.x += v.x; s.y += v.y; s.z += v.z; s.w += v.w;
    }
    *(float4*)(out + (size_t)m * NOUT + o4 * 4) = s;
}

// ---------------- launch ------------------------------------------------------
extern "C" void kernel_launch(void* const* d_in, const int* in_sizes, int n_in,
                              void* d_out, int out_size) {
    const float* topview = (const float*)d_in[0];
    const float* search  = (const float*)d_in[1];
    const float* w1      = (const float*)d_in[2];
    const float* b1      = (const float*)d_in[3];
    const float* w2      = (const float*)d_in[4];
    const float* b2      = (const float*)d_in[5];
    float* out = (float*)d_out;

    coords_kernel<<<BB, 512>>>(topview, w1, b1);
    gather_kernel<<<NPTS / 4, dim3(64, 4)>>>(search);
    sgemm_kernel<<<dim3(4, KSPLIT), 256>>>(w2);
    reduce_kernel<<<(BB * (NOUT / 4) + 127) / 128, 128>>>(b2, out);
}

// round 6
// speedup vs baseline: 2.5754x; 1.7404x over previous
#include <cuda_runtime.h>
#include <cstdint>
#include <math.h>

// Problem constants
#define BB 64
#define NPTS 2048
#define KTOT 98304          // NPTS * 48
#define NOUT 1000
#define IMG_H 1024
#define IMG_W 1024

// GEMM tiling
#define NT 128              // N per CTA
#define NTILES 8            // 8 * 128 = 1024 (padded N)
#define KSPLIT 37
#define KB 32               // K per stage
#define CHBASE 83           // 37*83 = 3071; ks==0 gets 84 -> 3072 stages total

// smem per buffer: STG(f32 B tile) 16384 | BS(bf16 hi/lo [n][k]) 128*144 | AH 64*80 | AL 64*80
#define SO_STG 0
#define SO_BS  16384
#define SO_AH  34816
#define SO_AL  39936
#define BUFSZ  45056
#define BS_STRIDE 144       // 64B hi + 64B lo + 16 pad
#define A_STRIDE  80        // 64B data + 16 pad

// ---------------- scratch ----------------
__device__ float g_xy[BB * NPTS * 2];
__device__ unsigned short g_Ah[(size_t)BB * KTOT];   // bf16 hi, [m][k]
__device__ unsigned short g_Al[(size_t)BB * KTOT];   // bf16 lo
__device__ float g_partial[(size_t)KSPLIT * BB * 1024];   // 9.7 MB

// ---------------- helpers ----------------
__device__ __forceinline__ void cp16(uint32_t dst, const void* src, int src_size) {
    asm volatile("cp.async.cg.shared.global [%0], [%1], 16, %2;"
                 :: "r"(dst), "l"(src), "r"(src_size));
}
__device__ __forceinline__ uint32_t smem_u32(const void* p) {
    return (uint32_t)__cvta_generic_to_shared(p);
}
__device__ __forceinline__ uint32_t cvt2bf(float f0, float f1) {
    uint32_t r;
    asm("cvt.rn.bf16x2.f32 %0, %1, %2;" : "=r"(r) : "f"(f1), "f"(f0));
    return r;  // f0 low half
}
__device__ __forceinline__ void split2(float f0, float f1, uint32_t& h, uint32_t& l) {
    h = cvt2bf(f0, f1);
    float h0 = __uint_as_float(h << 16);
    float h1 = __uint_as_float(h & 0xFFFF0000u);
    l = cvt2bf(f0 - h0, f1 - h1);
}
__device__ __forceinline__ void mma16816(float c[4], const uint32_t a[4],
                                         uint32_t b0, uint32_t b1) {
    asm volatile(
        "mma.sync.aligned.m16n8k16.row.col.f32.bf16.bf16.f32 "
        "{%0,%1,%2,%3}, {%4,%5,%6,%7}, {%8,%9}, {%0,%1,%2,%3};"
        : "+f"(c[0]), "+f"(c[1]), "+f"(c[2]), "+f"(c[3])
        : "r"(a[0]), "r"(a[1]), "r"(a[2]), "r"(a[3]), "r"(b0), "r"(b1));
}

// ---------------- kernel 1: resize + coords GEMM + sigmoid ----------------
__global__ void coords_kernel(const float* __restrict__ tv_img,
                              const float* __restrict__ w1,
                              const float* __restrict__ b1) {
    __shared__ float tv[48];
    int b = blockIdx.x;
    int tid = threadIdx.x;
    if (tid < 48) {
        int c = tid >> 4, rem = tid & 15, i = rem >> 2, j = rem & 3;
        int r0 = 7 + 16 * i, c0 = 7 + 16 * j;
        const float* base = tv_img + ((size_t)(b * 3 + c) * 64) * 64;
        float t0 = 0.5f * base[r0 * 64 + c0]     + 0.5f * base[(r0 + 1) * 64 + c0];
        float t1 = 0.5f * base[r0 * 64 + c0 + 1] + 0.5f * base[(r0 + 1) * 64 + c0 + 1];
        tv[tid] = 0.5f * t0 + 0.5f * t1;
    }
    __syncthreads();

    const float2* w1v = (const float2*)w1;
    const float2* b1v = (const float2*)b1;
    float2* xy = (float2*)g_xy;

    for (int n = tid; n < NPTS; n += blockDim.x) {
        float2 l = b1v[n];
        #pragma unroll
        for (int f = 0; f < 48; f++) {
            float2 w = w1v[(size_t)f * NPTS + n];
            l.x += tv[f] * w.x;
            l.y += tv[f] * w.y;
        }
        float sx = 1.0f / (1.0f + expf(-l.x));
        float sy = 1.0f / (1.0f + expf(-l.y));
        float2 p;
        p.x = sx * 1019.0f + 2.0f;
        p.y = sy * 1019.0f + 2.0f;
        xy[(size_t)b * NPTS + n] = p;
    }
}

// ---------------- kernel 2: gather -> bf16 hi/lo A[m][k] ----------------
__global__ void gather_kernel(const float* __restrict__ search) {
    int b = threadIdx.x;
    int n = blockIdx.x * 4 + threadIdx.y;

    const float2* xy = (const float2*)g_xy;
    float2 p = xy[(size_t)b * NPTS + n];
    float x0 = floorf(p.x), y0 = floorf(p.y);
    float fx = p.x - x0, fy = p.y - y0;
    int ix = (int)x0 - 2, iy = (int)y0 - 2;
    float wx0 = 1.0f - fx, wy0 = 1.0f - fy;

    const float* img = search + (size_t)b * (IMG_H * IMG_W * 3);

    float vals[48];
    float rowT[15], rowB[15];
    {
        const float* rp = img + ((size_t)ix * IMG_W + iy) * 3;
        #pragma unroll
        for (int t = 0; t < 15; t++) rowT[t] = __ldg(rp + t);
    }
    #pragma unroll
    for (int i = 0; i < 4; i++) {
        const float* rp = img + ((size_t)(ix + i + 1) * IMG_W + iy) * 3;
        #pragma unroll
        for (int t = 0; t < 15; t++) rowB[t] = __ldg(rp + t);
        #pragma unroll
        for (int j = 0; j < 4; j++) {
            #pragma unroll
            for (int ch = 0; ch < 3; ch++) {
                float top = wy0 * rowT[j * 3 + ch] + fy * rowT[j * 3 + 3 + ch];
                float bot = wy0 * rowB[j * 3 + ch] + fy * rowB[j * 3 + 3 + ch];
                vals[i * 12 + j * 3 + ch] = wx0 * top + fx * bot;
            }
        }
        #pragma unroll
        for (int t = 0; t < 15; t++) rowT[t] = rowB[t];
    }

    uint32_t hi[24], lo[24];
    #pragma unroll
    for (int q = 0; q < 24; q++) split2(vals[2 * q], vals[2 * q + 1], hi[q], lo[q]);

    size_t base = ((size_t)b * KTOT + (size_t)n * 48) * 2;   // bytes; 16-aligned
    #pragma unroll
    for (int u = 0; u < 6; u++) {
        *(uint4*)((char*)g_Ah + base + u * 16) =
            make_uint4(hi[4*u], hi[4*u+1], hi[4*u+2], hi[4*u+3]);
        *(uint4*)((char*)g_Al + base + u * 16) =
            make_uint4(lo[4*u], lo[4*u+1], lo[4*u+2], lo[4*u+3]);
    }
}

// ---------------- kernel 3: mma.sync bf16-split GEMM ----------------
__global__ void __launch_bounds__(256, 2) gemm_kernel(const float* __restrict__ w2) {
    extern __shared__ char smem[];
    const int tid = threadIdx.x;
    const int lane = tid & 31;
    const int w = tid >> 5;
    const int nt = blockIdx.x, ks = blockIdx.y;
    const int n0 = nt * NT;
    const int c0 = ks * CHBASE + (ks > 0 ? 1 : 0);
    const int nch = CHBASE + (ks == 0 ? 1 : 0);

    const int wm = w & 1, wn = w >> 1;
    const int m0 = wm * 32;
    const int n0w = wn * 32;

    uint32_t sbase = smem_u32(smem);

    float acc[2][4][4];
    #pragma unroll
    for (int mf = 0; mf < 2; mf++)
        #pragma unroll
        for (int ng = 0; ng < 4; ng++)
            #pragma unroll
            for (int q = 0; q < 4; q++) acc[mf][ng][q] = 0.0f;

    auto prefetch = [&](int s) {
        int buf = s & 1;
        uint32_t bb = sbase + buf * BUFSZ;
        int kg = (c0 + s) * KB;
        // B staging: 32 k-rows x 128 n f32 = 1024 16B chunks
        #pragma unroll
        for (int i = 0; i < 4; i++) {
            int g = tid + 256 * i;
            int kk = g >> 5, c4 = g & 31;
            int col = n0 + c4 * 4;
            int v = (col + 3 < NOUT) ? 16 : 0;
            const float* src = w2 + (size_t)(kg + kk) * NOUT + (v ? col : 0);
            cp16(bb + SO_STG + kk * 512 + c4 * 16, src, v);
        }
        // A hi/lo: 64 rows x 64B each
        int m = tid >> 2, c = tid & 3;
        size_t abyte = ((size_t)m * KTOT + kg) * 2 + c * 16;
        cp16(bb + SO_AH + m * A_STRIDE + c * 16, (const char*)g_Ah + abyte, 16);
        cp16(bb + SO_AL + m * A_STRIDE + c * 16, (const char*)g_Al + abyte, 16);
        asm volatile("cp.async.commit_group;");
    };

    prefetch(0);
    for (int s = 0; s < nch; s++) {
        int buf = s & 1;
        asm volatile("cp.async.wait_group 0;");
        __syncthreads();   // staging + A ready; all warps done with previous mma

        // convert w2 f32 -> bf16 hi/lo BS[n][k] (warp w owns k-quad 4w..4w+3)
        {
            const float* stg = (const float*)(smem + buf * BUFSZ + SO_STG);
            char* bsb = smem + buf * BUFSZ + SO_BS;
            int ck = w * 4;
            #pragma unroll
            for (int p = 0; p < 4; p++) {
                int n = lane + 32 * p;
                float v0 = stg[(ck + 0) * 128 + n];
                float v1 = stg[(ck + 1) * 128 + n];
                float v2 = stg[(ck + 2) * 128 + n];
                float v3 = stg[(ck + 3) * 128 + n];
                uint32_t h01, l01, h23, l23;
                split2(v0, v1, h01, l01);
                split2(v2, v3, h23, l23);
                char* brow = bsb + n * BS_STRIDE;
                *(uint2*)(brow + ck * 2)      = make_uint2(h01, h23);
                *(uint2*)(brow + 64 + ck * 2) = make_uint2(l01, l23);
            }
        }
        __syncthreads();   // BS ready

        if (s + 1 < nch) prefetch(s + 1);   // overlap DMA with mma

        // ---- mma over 2 k16 steps ----
        const char* AHp = smem + buf * BUFSZ + SO_AH;
        const char* ALp = smem + buf * BUFSZ + SO_AL;
        const char* BSp = smem + buf * BUFSZ + SO_BS;
        int arow = (m0 + (lane >> 2)) * A_STRIDE + (lane & 3) * 4;
        int brow0 = (n0w + (lane >> 2)) * BS_STRIDE + (lane & 3) * 4;

        #pragma unroll
        for (int s2 = 0; s2 < 2; s2++) {
            int ka = s2 * 32;
            uint32_t ah[2][4], al[2][4];
            #pragma unroll
            for (int mf = 0; mf < 2; mf++) {
                const char* ap = AHp + arow + mf * (16 * A_STRIDE) + ka;
                ah[mf][0] = *(const uint32_t*)(ap);
                ah[mf][1] = *(const uint32_t*)(ap + 8 * A_STRIDE);
                ah[mf][2] = *(const uint32_t*)(ap + 16);
                ah[mf][3] = *(const uint32_t*)(ap + 8 * A_STRIDE + 16);
                const char* ap2 = ALp + arow + mf * (16 * A_STRIDE) + ka;
                al[mf][0] = *(const uint32_t*)(ap2);
                al[mf][1] = *(const uint32_t*)(ap2 + 8 * A_STRIDE);
                al[mf][2] = *(const uint32_t*)(ap2 + 16);
                al[mf][3] = *(const uint32_t*)(ap2 + 8 * A_STRIDE + 16);
            }
            #pragma unroll
            for (int ng = 0; ng < 4; ng++) {
                const char* bp = BSp + brow0 + ng * (8 * BS_STRIDE) + ka;
                uint32_t bh0 = *(const uint32_t*)(bp);
                uint32_t bh1 = *(const uint32_t*)(bp + 16);
                uint32_t bl0 = *(const uint32_t*)(bp + 64);
                uint32_t bl1 = *(const uint32_t*)(bp + 80);
                #pragma unroll
                for (int mf = 0; mf < 2; mf++) {
                    mma16816(acc[mf][ng], ah[mf], bh0, bh1);
                    mma16816(acc[mf][ng], ah[mf], bl0, bl1);
                    mma16816(acc[mf][ng], al[mf], bh0, bh1);
                }
            }
        }
    }

    // epilogue: write fp32 partials
    float* dst = g_partial + (size_t)(ks * BB) * 1024;
    int r0 = m0 + (lane >> 2);
    int colb = n0 + n0w + 2 * (lane & 3);
    #pragma unroll
    for (int mf = 0; mf < 2; mf++) {
        #pragma unroll
        for (int ng = 0; ng < 4; ng++) {
            int row = r0 + mf * 16;
            int col = colb + ng * 8;
            *(float2*)(dst + (size_t)row * 1024 + col) =
                make_float2(acc[mf][ng][0], acc[mf][ng][1]);
            *(float2*)(dst + (size_t)(row + 8) * 1024 + col) =
                make_float2(acc[mf][ng][2], acc[mf][ng][3]);
        }
    }
}

// ---------------- kernel 4: reduce partials + bias ----------------
__global__ void reduce_kernel(const float* __restrict__ b2, float* __restrict__ out) {
    int idx4 = blockIdx.x * 128 + threadIdx.x;
    if (idx4 >= BB * (NOUT / 4)) return;
    int m = idx4 / (NOUT / 4);
    int o4 = idx4 % (NOUT / 4);
    float4 s = *(const float4*)(b2 + o4 * 4);
    const float* p = g_partial + (size_t)m * 1024 + o4 * 4;
    #pragma unroll
    for (int ks = 0; ks < KSPLIT; ks++) {
        float4 v = *(const float4*)(p + (size_t)ks * (BB * 1024));
        s.x += v.x; s.y += v.y; s.z += v.z; s.w += v.w;
    }
    *(float4*)(out + (size_t)m * NOUT + o4 * 4) = s;
}

// ---------------- launch ----------------
extern "C" void kernel_launch(void* const* d_in, const int* in_sizes, int n_in,
                              void* d_out, int out_size) {
    const float* topview = (const float*)d_in[0];
    const float* search  = (const float*)d_in[1];
    const float* w1      = (const float*)d_in[2];
    const float* b1      = (const float*)d_in[3];
    const float* w2      = (const float*)d_in[4];
    const float* b2      = (const float*)d_in[5];
    float* out = (float*)d_out;

    cudaFuncSetAttribute(gemm_kernel, cudaFuncAttributeMaxDynamicSharedMemorySize,
                         2 * BUFSZ);

    coords_kernel<<<BB, 512>>>(topview, w1, b1);
    gather_kernel<<<NPTS / 4, dim3(64, 4)>>>(search);
    gemm_kernel<<<dim3(NTILES, KSPLIT), 256, 2 * BUFSZ>>>(w2);
    reduce_kernel<<<(BB * (NOUT / 4) + 127) / 128, 128>>>(b2, out);
}

// round 7
// speedup vs baseline: 3.1085x; 1.2070x over previous
#include <cuda_runtime.h>
#include <cstdint>
#include <math.h>

// Problem constants
#define BB 64
#define NPTS 2048
#define KTOT 98304          // NPTS * 48
#define NOUT 1000
#define IMG_H 1024
#define IMG_W 1024

// GEMM tiling
#define NT 128              // N per CTA
#define NTILES 8            // 8 * 128 = 1024 (padded N)
#define KSPLIT 37
#define KB 32               // K per stage
#define CHBASE 83           // 37*83 = 3071; ks==0 gets 84 -> 3072 stages total

// smem per buffer: STG(f32 B tile) 16384 | BS(fp16 [n][k]) 128*80 | A(fp16 [m][k]) 64*80
#define SO_STG 0
#define SO_BS  16384
#define SO_A   26624
#define BUFSZ  31744
#define BS_STRIDE 80        // 64B data + 16 pad  (20 words: conflict-free frags)
#define A_STRIDE  80

// ---------------- scratch ----------------
__device__ float g_xy[BB * NPTS * 2];
__device__ unsigned short g_A[(size_t)BB * KTOT];        // fp16 A, [m][k], 12.6 MB
__device__ float g_partial[(size_t)KSPLIT * BB * 1024];  // 9.7 MB

// ---------------- helpers ----------------
__device__ __forceinline__ void cp16(uint32_t dst, const void* src, int src_size) {
    asm volatile("cp.async.cg.shared.global [%0], [%1], 16, %2;"
                 :: "r"(dst), "l"(src), "r"(src_size));
}
__device__ __forceinline__ uint32_t smem_u32(const void* p) {
    return (uint32_t)__cvta_generic_to_shared(p);
}
__device__ __forceinline__ uint32_t cvt2h(float f0, float f1) {
    uint32_t r;
    asm("cvt.rn.f16x2.f32 %0, %1, %2;" : "=r"(r) : "f"(f1), "f"(f0));
    return r;  // f0 in low half
}
__device__ __forceinline__ void mma16816(float c[4], const uint32_t a[4],
                                         uint32_t b0, uint32_t b1) {
    asm volatile(
        "mma.sync.aligned.m16n8k16.row.col.f32.f16.f16.f32 "
        "{%0,%1,%2,%3}, {%4,%5,%6,%7}, {%8,%9}, {%0,%1,%2,%3};"
        : "+f"(c[0]), "+f"(c[1]), "+f"(c[2]), "+f"(c[3])
        : "r"(a[0]), "r"(a[1]), "r"(a[2]), "r"(a[3]), "r"(b0), "r"(b1));
}

// ---------------- kernel 1: resize + coords GEMM + sigmoid ----------------
__global__ void coords_kernel(const float* __restrict__ tv_img,
                              const float* __restrict__ w1,
                              const float* __restrict__ b1) {
    __shared__ float tv[48];
    int b = blockIdx.x;
    int tid = threadIdx.x;
    if (tid < 48) {
        int c = tid >> 4, rem = tid & 15, i = rem >> 2, j = rem & 3;
        int r0 = 7 + 16 * i, c0 = 7 + 16 * j;
        const float* base = tv_img + ((size_t)(b * 3 + c) * 64) * 64;
        float t0 = 0.5f * base[r0 * 64 + c0]     + 0.5f * base[(r0 + 1) * 64 + c0];
        float t1 = 0.5f * base[r0 * 64 + c0 + 1] + 0.5f * base[(r0 + 1) * 64 + c0 + 1];
        tv[tid] = 0.5f * t0 + 0.5f * t1;
    }
    __syncthreads();

    const float2* w1v = (const float2*)w1;
    const float2* b1v = (const float2*)b1;
    float2* xy = (float2*)g_xy;

    for (int n = tid; n < NPTS; n += blockDim.x) {
        float2 l = b1v[n];
        #pragma unroll
        for (int f = 0; f < 48; f++) {
            float2 w = w1v[(size_t)f * NPTS + n];
            l.x += tv[f] * w.x;
            l.y += tv[f] * w.y;
        }
        float sx = 1.0f / (1.0f + expf(-l.x));
        float sy = 1.0f / (1.0f + expf(-l.y));
        float2 p;
        p.x = sx * 1019.0f + 2.0f;
        p.y = sy * 1019.0f + 2.0f;
        xy[(size_t)b * NPTS + n] = p;
    }
}

// ---------------- kernel 2: gather -> fp16 A[m][k] ----------------
__global__ void gather_kernel(const float* __restrict__ search) {
    int b = threadIdx.x;
    int n = blockIdx.x * 4 + threadIdx.y;

    const float2* xy = (const float2*)g_xy;
    float2 p = xy[(size_t)b * NPTS + n];
    float x0 = floorf(p.x), y0 = floorf(p.y);
    float fx = p.x - x0, fy = p.y - y0;
    int ix = (int)x0 - 2, iy = (int)y0 - 2;
    float wx0 = 1.0f - fx, wy0 = 1.0f - fy;

    const float* img = search + (size_t)b * (IMG_H * IMG_W * 3);

    float vals[48];
    float rowT[15], rowB[15];
    {
        const float* rp = img + ((size_t)ix * IMG_W + iy) * 3;
        #pragma unroll
        for (int t = 0; t < 15; t++) rowT[t] = __ldg(rp + t);
    }
    #pragma unroll
    for (int i = 0; i < 4; i++) {
        const float* rp = img + ((size_t)(ix + i + 1) * IMG_W + iy) * 3;
        #pragma unroll
        for (int t = 0; t < 15; t++) rowB[t] = __ldg(rp + t);
        #pragma unroll
        for (int j = 0; j < 4; j++) {
            #pragma unroll
            for (int ch = 0; ch < 3; ch++) {
                float top = wy0 * rowT[j * 3 + ch] + fy * rowT[j * 3 + 3 + ch];
                float bot = wy0 * rowB[j * 3 + ch] + fy * rowB[j * 3 + 3 + ch];
                vals[i * 12 + j * 3 + ch] = wx0 * top + fx * bot;
            }
        }
        #pragma unroll
        for (int t = 0; t < 15; t++) rowT[t] = rowB[t];
    }

    uint32_t h[24];
    #pragma unroll
    for (int q = 0; q < 24; q++) h[q] = cvt2h(vals[2 * q], vals[2 * q + 1]);

    size_t base = ((size_t)b * KTOT + (size_t)n * 48) * 2;   // bytes; 16-aligned
    #pragma unroll
    for (int u = 0; u < 6; u++) {
        *(uint4*)((char*)g_A + base + u * 16) =
            make_uint4(h[4*u], h[4*u+1], h[4*u+2], h[4*u+3]);
    }
}

// ---------------- kernel 3: mma.sync fp16 GEMM ----------------
__global__ void __launch_bounds__(256, 2) gemm_kernel(const float* __restrict__ w2) {
    extern __shared__ char smem[];
    const int tid = threadIdx.x;
    const int lane = tid & 31;
    const int w = tid >> 5;
    const int nt = blockIdx.x, ks = blockIdx.y;
    const int n0 = nt * NT;
    const int c0 = ks * CHBASE + (ks > 0 ? 1 : 0);
    const int nch = CHBASE + (ks == 0 ? 1 : 0);

    const int wm = w & 1, wn = w >> 1;
    const int m0 = wm * 32;
    const int n0w = wn * 32;

    uint32_t sbase = smem_u32(smem);

    float acc[2][4][4];
    #pragma unroll
    for (int mf = 0; mf < 2; mf++)
        #pragma unroll
        for (int ng = 0; ng < 4; ng++)
            #pragma unroll
            for (int q = 0; q < 4; q++) acc[mf][ng][q] = 0.0f;

    auto prefetch = [&](int s) {
        int buf = s & 1;
        uint32_t bb = sbase + buf * BUFSZ;
        int kg = (c0 + s) * KB;
        // B staging: 32 k-rows x 128 n f32 = 1024 16B chunks
        #pragma unroll
        for (int i = 0; i < 4; i++) {
            int g = tid + 256 * i;
            int kk = g >> 5, c4 = g & 31;
            int col = n0 + c4 * 4;
            int v = (col + 3 < NOUT) ? 16 : 0;
            const float* src = w2 + (size_t)(kg + kk) * NOUT + (v ? col : 0);
            cp16(bb + SO_STG + kk * 512 + c4 * 16, src, v);
        }
        // A fp16: 64 rows x 64B
        int m = tid >> 2, c = tid & 3;
        size_t abyte = ((size_t)m * KTOT + kg) * 2 + c * 16;
        cp16(bb + SO_A + m * A_STRIDE + c * 16, (const char*)g_A + abyte, 16);
        asm volatile("cp.async.commit_group;");
    };

    prefetch(0);
    for (int s = 0; s < nch; s++) {
        int buf = s & 1;
        asm volatile("cp.async.wait_group 0;");
        __syncthreads();   // staging + A ready; prev mma done with this buffer

        // convert w2 f32 -> fp16 BS[n][k] (warp w owns k-quad 4w..4w+3)
        {
            const float* stg = (const float*)(smem + buf * BUFSZ + SO_STG);
            char* bsb = smem + buf * BUFSZ + SO_BS;
            int ck = w * 4;
            #pragma unroll
            for (int p = 0; p < 4; p++) {
                int n = lane + 32 * p;
                float v0 = stg[(ck + 0) * 128 + n];
                float v1 = stg[(ck + 1) * 128 + n];
                float v2 = stg[(ck + 2) * 128 + n];
                float v3 = stg[(ck + 3) * 128 + n];
                uint32_t h01 = cvt2h(v0, v1);
                uint32_t h23 = cvt2h(v2, v3);
                *(uint2*)(bsb + n * BS_STRIDE + ck * 2) = make_uint2(h01, h23);
            }
        }
        __syncthreads();   // BS ready

        if (s + 1 < nch) prefetch(s + 1);   // overlap DMA with mma

        const char* Ap  = smem + buf * BUFSZ + SO_A;
        const char* BSp = smem + buf * BUFSZ + SO_BS;
        int arow  = (m0 + (lane >> 2)) * A_STRIDE + (lane & 3) * 4;
        int brow0 = (n0w + (lane >> 2)) * BS_STRIDE + (lane & 3) * 4;

        #pragma unroll
        for (int s2 = 0; s2 < 2; s2++) {
            int ka = s2 * 32;
            uint32_t a[2][4];
            #pragma unroll
            for (int mf = 0; mf < 2; mf++) {
                const char* ap = Ap + arow + mf * (16 * A_STRIDE) + ka;
                a[mf][0] = *(const uint32_t*)(ap);
                a[mf][1] = *(const uint32_t*)(ap + 8 * A_STRIDE);
                a[mf][2] = *(const uint32_t*)(ap + 16);
                a[mf][3] = *(const uint32_t*)(ap + 8 * A_STRIDE + 16);
            }
            #pragma unroll
            for (int ng = 0; ng < 4; ng++) {
                const char* bp = BSp + brow0 + ng * (8 * BS_STRIDE) + ka;
                uint32_t b0 = *(const uint32_t*)(bp);
                uint32_t b1 = *(const uint32_t*)(bp + 16);
                #pragma unroll
                for (int mf = 0; mf < 2; mf++)
                    mma16816(acc[mf][ng], a[mf], b0, b1);
            }
        }
    }

    // epilogue: write fp32 partials
    float* dst = g_partial + (size_t)(ks * BB) * 1024;
    int r0 = m0 + (lane >> 2);
    int colb = n0 + n0w + 2 * (lane & 3);
    #pragma unroll
    for (int mf = 0; mf < 2; mf++) {
        #pragma unroll
        for (int ng = 0; ng < 4; ng++) {
            int row = r0 + mf * 16;
            int col = colb + ng * 8;
            *(float2*)(dst + (size_t)row * 1024 + col) =
                make_float2(acc[mf][ng][0], acc[mf][ng][1]);
            *(float2*)(dst + (size_t)(row + 8) * 1024 + col) =
                make_float2(acc[mf][ng][2], acc[mf][ng][3]);
        }
    }
}

// ---------------- kernel 4: reduce partials + bias ----------------
__global__ void reduce_kernel(const float* __restrict__ b2, float* __restrict__ out) {
    int idx4 = blockIdx.x * 128 + threadIdx.x;
    if (idx4 >= BB * (NOUT / 4)) return;
    int m = idx4 / (NOUT / 4);
    int o4 = idx4 % (NOUT / 4);
    float4 s = *(const float4*)(b2 + o4 * 4);
    const float* p = g_partial + (size_t)m * 1024 + o4 * 4;
    #pragma unroll
    for (int ks = 0; ks < KSPLIT; ks++) {
        float4 v = *(const float4*)(p + (size_t)ks * (BB * 1024));
        s.x += v.x; s.y += v.y; s.z += v.z; s.w += v.w;
    }
    *(float4*)(out + (size_t)m * NOUT + o4 * 4) = s;
}

// ---------------- launch ----------------
extern "C" void kernel_launch(void* const* d_in, const int* in_sizes, int n_in,
                              void* d_out, int out_size) {
    const float* topview = (const float*)d_in[0];
    const float* search  = (const float*)d_in[1];
    const float* w1      = (const float*)d_in[2];
    const float* b1      = (const float*)d_in[3];
    const float* w2      = (const float*)d_in[4];
    const float* b2      = (const float*)d_in[5];
    float* out = (float*)d_out;

    cudaFuncSetAttribute(gemm_kernel, cudaFuncAttributeMaxDynamicSharedMemorySize,
                         2 * BUFSZ);

    coords_kernel<<<BB, 512>>>(topview, w1, b1);
    gather_kernel<<<NPTS / 4, dim3(64, 4)>>>(search);
    gemm_kernel<<<dim3(NTILES, KSPLIT), 256, 2 * BUFSZ>>>(w2);
    reduce_kernel<<<(BB * (NOUT / 4) + 127) / 128, 128>>>(b2, out);
}